// round 11
// baseline (speedup 1.0000x reference)
#include <cuda_runtime.h>
#include <cstdint>

// LSTM decoder, persistent per-CTA recurrence. 512 threads, G=8 rows/thread.
// warp w (0..15): units u0=(w&7)*8+ulow, u1=u0+64; bp-half bph=w>>3
//   (bph0: batch-pairs 0..3, bph1: 4..6). lane: kg=lane>>3 (32 k's each).
// Quad-0 weights in SMEM, quad-1 streamed LDG. kg-partials reduced by warp
// shuffles; each lane ends with complete (i,f,g,o) quads -> c in registers.
// B=2048, L=64, H=128, 4H=512, O=64, T=512, fp32.
// Identity: x_t == h_t for t>=1 => gates = h @ (W_ih+W_hh)^T + (b_ih+b_hh).
// t==0: x=0 => gates = h0 @ W_hh^T + (b_ih+b_hh).

typedef unsigned long long ull;

#define Lq   64
#define Hq   128
#define Oq   64
#define Tq   512
#define HS   20     // h_s row stride in floats (80 B)

// Quad-packed weights: g_Wq[k*128 + u] = (W[u][k], W[u+128][k], W[u+256][k], W[u+384][k])
__device__ float4 g_Wq [Hq * Hq];   // combined W_ih + W_hh
__device__ float4 g_Whq[Hq * Hq];   // W_hh only (step 0)

// ---------- helpers ----------
__device__ __forceinline__ ull fma2(ull a, ull b, ull c) {
    ull d; asm("fma.rn.f32x2 %0, %1, %2, %3;" : "=l"(d) : "l"(a), "l"(b), "l"(c)); return d;
}
__device__ __forceinline__ ull add2(ull a, ull b) {
    ull d; asm("add.rn.f32x2 %0, %1, %2;" : "=l"(d) : "l"(a), "l"(b)); return d;
}
__device__ __forceinline__ ull dup2(float x) {
    ull d; asm("mov.b64 %0, {%1, %1};" : "=l"(d) : "f"(x)); return d;
}
__device__ __forceinline__ ull pack2(float lo, float hi) {
    ull d; asm("mov.b64 %0, {%1, %2};" : "=l"(d) : "f"(lo), "f"(hi)); return d;
}
__device__ __forceinline__ void unpk(ull a, float& lo, float& hi) {
    asm("mov.b64 {%0, %1}, %2;" : "=f"(lo), "=f"(hi) : "l"(a));
}
__device__ __forceinline__ void ldsv2(ull& a, ull& b, unsigned addr) {
    asm volatile("ld.shared.v2.u64 {%0, %1}, [%2];" : "=l"(a), "=l"(b) : "r"(addr));
}
__device__ __forceinline__ ull lds64(unsigned addr) {
    ull a; asm volatile("ld.shared.u64 %0, [%1];" : "=l"(a) : "r"(addr)); return a;
}
__device__ __forceinline__ void sts64(unsigned addr, ull v) {
    asm volatile("st.shared.u64 [%0], %1;" :: "r"(addr), "l"(v));
}
__device__ __forceinline__ void sts32(unsigned addr, float v) {
    asm volatile("st.shared.f32 [%0], %1;" :: "r"(addr), "f"(v));
}
__device__ __forceinline__ unsigned sm_u32(const void* p) {
    unsigned r;
    asm("{ .reg .u64 t; cvta.to.shared.u64 t, %1; cvt.u32.u64 %0, t; }" : "=r"(r) : "l"(p));
    return r;
}
__device__ __forceinline__ ull shflx64(ull v, int m) {
    return __shfl_xor_sync(0xffffffffu, v, m);
}
__device__ __forceinline__ float sigf(float x)   { return __fdividef(1.f, 1.f + __expf(-x)); }
__device__ __forceinline__ float tanhf2(float x) { return __fdividef(2.f, 1.f + __expf(-2.f * x)) - 1.f; }

// ---------- prep: quad-pack transposed weights ----------
__global__ void decoder_prep(const float* __restrict__ Wih, const float* __restrict__ Whh) {
    int i = blockIdx.x * blockDim.x + threadIdx.x;   // i = k*128 + u
    if (i < Hq * Hq) {
        int u = i & 127, k = i >> 7;
        float4 wh, wc;
        wh.x = Whh[u * Hq + k];          wc.x = Wih[u * Hq + k]          + wh.x;
        wh.y = Whh[(u + 128) * Hq + k];  wc.y = Wih[(u + 128) * Hq + k]  + wh.y;
        wh.z = Whh[(u + 256) * Hq + k];  wc.z = Wih[(u + 256) * Hq + k]  + wh.z;
        wh.w = Whh[(u + 384) * Hq + k];  wc.w = Wih[(u + 384) * Hq + k]  + wh.w;
        g_Wq[i] = wc;  g_Whq[i] = wh;
    }
}

// ---------- fused GEMM: 8 gate rows + 1 out row over 32 k's, P batch-pairs ----------
// T0: step 0 -> quad0 via LDG from g_Whq (w0g); else quad0 via SMEM (w0s).
template <int P, bool T0>
__device__ __forceinline__ void gemm32(
    const float4* __restrict__ w0s,   // SMEM Wq_s + kg*32*64 + u0 (stride 64)
    const float4* __restrict__ w0g,   // g_Whq + kg*32*128 + u0    (stride 128)
    const float4* __restrict__ w1g,   // (T0? g_Whq : g_Wq) + kg*32*128 + u1
    const float*  __restrict__ wo_sp, // SMEM Wo_s + kg*32*64 + u0
    unsigned hbk,                     // h_s byte addr + kg*32*80 (+32 if bph1)
    ull (&A)[2][4][4], ull (&Aw)[4])
{
#pragma unroll 4
    for (int i = 0; i < 32; i++) {
        float4 w0 = T0 ? __ldg(w0g + i * 128) : w0s[i * 64];
        float4 w1 = __ldg(w1g + i * 128);
        float  wo = wo_sp[i * 64];
        unsigned a = hbk + (unsigned)(i * (HS * 4));
        ull hh[4];
        if (P == 4) {
            ldsv2(hh[0], hh[1], a);        // slots 0..3
            ldsv2(hh[2], hh[3], a + 16);   // slots 4..7
        } else {
            ldsv2(hh[0], hh[1], a);        // slots 8..11 (hbk pre-offset +32)
            hh[2] = lds64(a + 16);         // slots 12,13
        }
        ull wi0 = dup2(w0.x), wf0 = dup2(w0.y), wg0 = dup2(w0.z), wo0 = dup2(w0.w);
        ull wi1 = dup2(w1.x), wf1 = dup2(w1.y), wg1 = dup2(w1.z), wo1 = dup2(w1.w);
        ull wwo = dup2(wo);
#pragma unroll
        for (int bp = 0; bp < P; bp++) {
            A[0][0][bp] = fma2(wi0, hh[bp], A[0][0][bp]);
            A[0][1][bp] = fma2(wf0, hh[bp], A[0][1][bp]);
            A[0][2][bp] = fma2(wg0, hh[bp], A[0][2][bp]);
            A[0][3][bp] = fma2(wo0, hh[bp], A[0][3][bp]);
            A[1][0][bp] = fma2(wi1, hh[bp], A[1][0][bp]);
            A[1][1][bp] = fma2(wf1, hh[bp], A[1][1][bp]);
            A[1][2][bp] = fma2(wg1, hh[bp], A[1][2][bp]);
            A[1][3][bp] = fma2(wo1, hh[bp], A[1][3][bp]);
            Aw[bp]      = fma2(wwo, hh[bp], Aw[bp]);
        }
    }
}

// SMEM layout (float offsets):
//   Wq_s [128k][64u] f4 @ 0      (32768)  quad weights, units 0..63
//   Wo_s [128k][64o]    @ 32768  ( 8192)  Wo transposed
//   h_s  [128][20]      @ 40960  ( 2560)  h transposed [k][slot]
//   ob   [64o][15]      @ 43520  (  960)  out staging
#define OFF_WOS 32768
#define OFF_H   40960
#define OFF_OB  43520
#define SMEM_FLOATS 44480
#define SMEM_BYTES  (SMEM_FLOATS * 4)

__global__ void __launch_bounds__(512, 1) decoder_main(
    const float* __restrict__ latent, const float* __restrict__ fc_w, const float* __restrict__ fc_b,
    const float* __restrict__ b_ih,   const float* __restrict__ b_hh,
    const float* __restrict__ Wo,     const float* __restrict__ bo,
    float* __restrict__ out)
{
    extern __shared__ float sm[];
    float4* Wq_s = reinterpret_cast<float4*>(sm);
    float* Wo_s = sm + OFF_WOS;
    float* h_s  = sm + OFF_H;
    float* ob   = sm + OFF_OB;

    const int tid  = threadIdx.x;
    const int lane = tid & 31;
    const int warp = tid >> 5;                 // 0..15
    const int kg   = lane >> 3;                // k-group 0..3
    const int kgb0 = kg & 1;
    const int kgb1 = kg >> 1;
    const int u0   = (warp & 7) * 8 + (lane & 7);  // 0..63
    const int u1   = u0 + 64;
    const int bph  = warp >> 3;                // 0: bp0-3, 1: bp4-6
    const int cta  = blockIdx.x;
    int bstart, nb;
    if (cta < 124) { bstart = cta * 14;                nb = 14; }
    else           { bstart = 1736 + (cta - 124) * 13; nb = 13; }

    // Stage quad-0 weights (units 0..63) and Wo into SMEM.
    for (int i = tid; i < Hq * 64; i += 512) {
        int k = i >> 6, u = i & 63;
        Wq_s[i] = g_Wq[k * Hq + u];
    }
    for (int i = tid; i < Hq * Oq; i += 512) {
        int k = i >> 6, o = i & 63;
        Wo_s[i] = Wo[o * Hq + k];
    }
    for (int i = tid; i < Hq * HS; i += 512) h_s[i] = 0.f;
    __syncthreads();

    // h0 = latent @ fc_w^T + fc_b  (pad slots stay 0)
    for (int i = tid; i < 14 * Hq; i += 512) {
        int slot = i >> 7, hk = i & 127;
        float acc = 0.f;
        if (slot < nb) {
            acc = fc_b[hk];
            const float* lp = latent + (size_t)(bstart + slot) * Lq;
            const float* wp = fc_w + hk * Lq;
#pragma unroll 8
            for (int l = 0; l < Lq; l++) acc += lp[l] * wp[l];
        }
        h_s[hk * HS + slot] = acc;
    }

    // Biases: only kg==0 lanes inject them (summed once across the xor-tree).
    ull bb[2][4];
#pragma unroll
    for (int us = 0; us < 2; us++) {
        int u = us ? u1 : u0;
#pragma unroll
        for (int g = 0; g < 4; g++) {
            float v = b_ih[g * 128 + u] + b_hh[g * 128 + u];
            bb[us][g] = (kg == 0) ? dup2(v) : 0ull;
        }
    }
    const ull bow = (kg == 0) ? dup2(bo[u0]) : 0ull;

    const int P = bph ? 3 : 4;
    // Register-resident cell state. Post-reduction ownership:
    //   unit = kgb1 ? u1 : u0;  bp = bph*4 + (bph0: kgb0*2+j, j=0,1)
    //                               (bph1: kgb0==0 -> 4+j (j=0,1); kgb0==1 -> 6)
    ull cR[2] = {0ull, 0ull};
    const int U = kgb1 ? u1 : u0;

    const unsigned hb  = sm_u32(h_s);
    const unsigned obb = sm_u32(ob);
    const unsigned hbk = hb + (unsigned)(kg * 32 * (HS * 4) + bph * 32);
    const float4* w0s = Wq_s  + kg * 32 * 64 + u0;
    const float4* w0g = g_Whq + kg * 32 * Hq + u0;
    const float4* wh1 = g_Whq + kg * 32 * Hq + u1;
    const float4* wc1 = g_Wq  + kg * 32 * Hq + u1;
    const float*  wo_sp = Wo_s + kg * 32 * Oq + u0;
    __syncthreads();

    for (int t = 0; t < Tq; t++) {
        // ---- phase 1: fused gate+out GEMM over this lane's 32 k's ----
        ull A[2][4][4], Aw[4];
#pragma unroll
        for (int us = 0; us < 2; us++)
#pragma unroll
            for (int g = 0; g < 4; g++)
#pragma unroll
                for (int bp = 0; bp < 4; bp++) A[us][g][bp] = bb[us][g];
#pragma unroll
        for (int j = 0; j < 4; j++) Aw[j] = bow;

        if (bph == 0) {
            if (t == 0) gemm32<4, true >(w0s, w0g, wh1, wo_sp, hbk, A, Aw);
            else        gemm32<4, false>(w0s, w0g, wc1, wo_sp, hbk, A, Aw);
        } else {
            if (t == 0) gemm32<3, true >(w0s, w0g, wh1, wo_sp, hbk, A, Aw);
            else        gemm32<3, false>(w0s, w0g, wc1, wo_sp, hbk, A, Aw);
        }

        // ---- kg reduce-scatter ----
        // Stage A (xor 16): kgb1=0 keeps quad0's P accums, kgb1=1 keeps quad1's.
        ull K[4][4];
#pragma unroll
        for (int g = 0; g < 4; g++)
#pragma unroll
            for (int bp = 0; bp < 4; bp++) {
                ull snd  = kgb1 ? A[0][g][bp] : A[1][g][bp];
                ull rcv  = shflx64(snd, 16);
                ull mine = kgb1 ? A[1][g][bp] : A[0][g][bp];
                K[g][bp] = add2(mine, rcv);
            }
        // Stage B (xor 8): split bp. bph0: kgb0=0 keeps idx{0,1}, kgb0=1 idx{2,3}.
        //                  bph1: kgb0=0 keeps idx{0,1}, kgb0=1 idx{2}.
#pragma unroll
        for (int g = 0; g < 4; g++)
#pragma unroll
            for (int j = 0; j < 2; j++) {
                ull snd;
                if (bph == 0) snd = kgb0 ? K[g][j] : K[g][2 + j];
                else          snd = kgb0 ? K[g][j] : ((j == 0) ? K[g][2] : K[g][0]);
                ull rcv = shflx64(snd, 8);
                if (bph == 0) {
                    if (!kgb0) K[g][j]     = add2(K[g][j],     rcv);
                    else       K[g][2 + j] = add2(K[g][2 + j], rcv);
                } else {
                    if (!kgb0)       K[g][j] = add2(K[g][j], rcv);
                    else if (j == 0) K[g][2] = add2(K[g][2], rcv);
                }
            }
        // Out-row full butterfly over kg.
#pragma unroll
        for (int j = 0; j < 4; j++) Aw[j] = add2(Aw[j], shflx64(Aw[j], 16));
#pragma unroll
        for (int j = 0; j < 4; j++) Aw[j] = add2(Aw[j], shflx64(Aw[j], 8));

        __syncthreads();   // all h_s reads of this step done

        // ---- phase 2: elementwise cell update in registers; write h to SMEM ----
#pragma unroll
        for (int j = 0; j < 2; j++) {
            bool active = (bph == 0) || (!kgb0) || (j == 0);
            if (active) {
                int idx = (bph == 0) ? (kgb0 * 2 + j) : (kgb0 ? 2 : j);
                int bp  = (bph == 0) ? idx : (kgb0 ? 6 : 4 + j);
                float gi0, gi1, gf0, gf1, gg0, gg1, go0, go1, cc0, cc1;
                unpk(K[0][idx], gi0, gi1);
                unpk(K[1][idx], gf0, gf1);
                unpk(K[2][idx], gg0, gg1);
                unpk(K[3][idx], go0, go1);
                unpk(cR[j], cc0, cc1);
                float nc0 = sigf(gf0) * cc0 + sigf(gi0) * tanhf2(gg0);
                float nc1 = sigf(gf1) * cc1 + sigf(gi1) * tanhf2(gg1);
                float hv0 = sigf(go0) * tanhf2(nc0);
                float hv1 = sigf(go1) * tanhf2(nc1);
                cR[j] = pack2(nc0, nc1);
                sts64(hb + (unsigned)(U * (HS * 4) + bp * 8), pack2(hv0, hv1));
            }
        }

        // ---- stage out[t-1]: kg==0 lanes write full sums ----
        if (kg == 0) {
            unsigned ow = obb + (unsigned)(u0 * 60);   // 15 floats/row
#pragma unroll
            for (int j = 0; j < 4; j++) {
                if (j < P) {
                    int s0 = bph * 8 + 2 * j;
                    float lo, hi;
                    unpk(Aw[j], lo, hi);
                    sts32(ow + (unsigned)(s0 * 4),     lo);
                    sts32(ow + (unsigned)(s0 * 4 + 4), hi);
                }
            }
        }
        __syncthreads();

        // ---- coalesced store of out[t-1]: warps 0-6 -> slots 2w, 2w+1 ----
        if (t > 0 && warp < 7) {
#pragma unroll
            for (int si = 0; si < 2; si++) {
                int s = 2 * warp + si;
                if (s < nb) {
                    float v0 = ob[lane * 15 + s];
                    float v1 = ob[(lane + 32) * 15 + s];
                    size_t base = ((size_t)(bstart + s) * Tq + (t - 1)) * Oq;
                    out[base + lane]      = v0;
                    out[base + lane + 32] = v1;
                }
            }
        }
    }

    // ---- tail: out[T-1] from final h ----
    {
        ull Aw[4];
#pragma unroll
        for (int j = 0; j < 4; j++) Aw[j] = bow;
#pragma unroll 4
        for (int i = 0; i < 32; i++) {
            float wo = wo_sp[i * 64];
            ull wwo = dup2(wo);
            unsigned a = hbk + (unsigned)(i * (HS * 4));
            ull hh[4];
            if (bph == 0) { ldsv2(hh[0], hh[1], a); ldsv2(hh[2], hh[3], a + 16); }
            else          { ldsv2(hh[0], hh[1], a); hh[2] = lds64(a + 16); hh[3] = 0ull; }
#pragma unroll
            for (int j = 0; j < 4; j++)
                if (j < P) Aw[j] = fma2(wwo, hh[j], Aw[j]);
        }
#pragma unroll
        for (int j = 0; j < 4; j++) Aw[j] = add2(Aw[j], shflx64(Aw[j], 16));
#pragma unroll
        for (int j = 0; j < 4; j++) Aw[j] = add2(Aw[j], shflx64(Aw[j], 8));

        __syncthreads();   // out[T-2] readers done with ob before overwrite

        if (kg == 0) {
            unsigned ow = obb + (unsigned)(u0 * 60);
#pragma unroll
            for (int j = 0; j < 4; j++) {
                if (j < P) {
                    int s0 = bph * 8 + 2 * j;
                    float lo, hi;
                    unpk(Aw[j], lo, hi);
                    sts32(ow + (unsigned)(s0 * 4),     lo);
                    sts32(ow + (unsigned)(s0 * 4 + 4), hi);
                }
            }
        }
        __syncthreads();
        if (warp < 7) {
#pragma unroll
            for (int si = 0; si < 2; si++) {
                int s = 2 * warp + si;
                if (s < nb) {
                    float v0 = ob[lane * 15 + s];
                    float v1 = ob[(lane + 32) * 15 + s];
                    size_t base = ((size_t)(bstart + s) * Tq + (Tq - 1)) * Oq;
                    out[base + lane]      = v0;
                    out[base + lane + 32] = v1;
                }
            }
        }
    }
}

extern "C" void kernel_launch(void* const* d_in, const int* in_sizes, int n_in,
                              void* d_out, int out_size) {
    const float* latent = (const float*)d_in[0];
    const float* fc_w   = (const float*)d_in[1];
    const float* fc_b   = (const float*)d_in[2];
    const float* W_ih   = (const float*)d_in[3];
    const float* W_hh   = (const float*)d_in[4];
    const float* b_ih   = (const float*)d_in[5];
    const float* b_hh   = (const float*)d_in[6];
    const float* Wo     = (const float*)d_in[7];
    const float* bo     = (const float*)d_in[8];
    float* out = (float*)d_out;

    cudaFuncSetAttribute(decoder_main,
                         cudaFuncAttributeMaxDynamicSharedMemorySize, SMEM_BYTES);

    decoder_prep<<<(Hq * Hq + 511) / 512, 512>>>(W_ih, W_hh);
    decoder_main<<<148, 512, SMEM_BYTES>>>(latent, fc_w, fc_b, b_ih, b_hh, Wo, bo, out);
}

// round 13
// speedup vs baseline: 2.8641x; 2.8641x over previous
#include <cuda_runtime.h>
#include <cuda_fp16.h>
#include <cstdint>

// LSTM decoder on legacy tensor-core path (mma.sync m16n8k16 + ldmatrix),
// compilable at compute_100 (no tcgen05 / sm_100a features needed).
// One persistent CTA per SM (148), 256 threads (8 warps), batch slice 14 (N=16 pad).
// gates[512x16] = Wc[512x128] @ h^T as m16n8k16 tiles, fp32 register accum.
// Warp w owns units [16w,16w+16): its 4 gate D-frags are slot-aligned across
// i,f,g,o -> elementwise in registers, c register-resident.
// Split precision: h = hhi+hlo (exact); f,g gate weights hi+lo; i,o,Wo hi-only.
// Identity: x_t == h_t for t>=1 => Wc = W_ih + W_hh. Step 0 runs the same MMA
// path with A tiles = W_hh, then A is rewritten with Wc.
// out_{t-1} = Wo @ h_t fused into iteration t (B tiles hold h_t).

#define Tq 512
#define Oq 64
#define Lq 64

// SMEM byte offsets. A regions: [rows][128 k] fp16, 256B/row, XOR-swizzled.
#define A_HI   0u        // 512 rows (4 gate tiles of 128 rows)     131072 B
#define A_GLO  131072u   // 128 rows: g-gate lo                      32768 B
#define A_FLO  163840u   // 128 rows: f-gate lo                      32768 B
#define A_WO   196608u   // 64 rows: Wo hi                           16384 B
#define H_HI   212992u   // h hi: [16 n][128 k] fp16, 272B row stride 4352 B
#define H_LO   217344u   // h lo                                      4352 B
#define SMEM_BYTES 221696u
#define HSTB   272u

// ---------- helpers ----------
__device__ __forceinline__ unsigned sm_u32(const void* p) {
    unsigned r;
    asm("{ .reg .u64 t; cvta.to.shared.u64 t, %1; cvt.u32.u64 %0, t; }" : "=r"(r) : "l"(p));
    return r;
}
__device__ __forceinline__ float sigf(float x)   { return __fdividef(1.f, 1.f + __expf(-x)); }
__device__ __forceinline__ float tanhf2(float x) { return __fdividef(2.f, 1.f + __expf(-2.f * x)) - 1.f; }

// Swizzle: o ^ ((row&7)<<4). Keeps 16B segments intact; ldmatrix conflict-free.
__device__ __forceinline__ unsigned aswz(unsigned o) { return o ^ ((o >> 4) & 0x70u); }

__device__ __forceinline__ void ldmx4(unsigned* a, unsigned addr) {
    asm volatile("ldmatrix.sync.aligned.m8n8.x4.shared.b16 {%0,%1,%2,%3}, [%4];"
        : "=r"(a[0]), "=r"(a[1]), "=r"(a[2]), "=r"(a[3]) : "r"(addr));
}
__device__ __forceinline__ void mma16(float* d, const unsigned* a, unsigned b0, unsigned b1) {
    asm volatile(
        "mma.sync.aligned.m16n8k16.row.col.f32.f16.f16.f32 "
        "{%0,%1,%2,%3}, {%4,%5,%6,%7}, {%8,%9}, {%0,%1,%2,%3};"
        : "+f"(d[0]), "+f"(d[1]), "+f"(d[2]), "+f"(d[3])
        : "r"(a[0]), "r"(a[1]), "r"(a[2]), "r"(a[3]), "r"(b0), "r"(b1));
}

// Fill A tiles from weights. comb=false: W_hh (step 0); true: W_ih+W_hh.
__device__ __forceinline__ void init_A(char* smc, const float* __restrict__ W_ih,
                                       const float* __restrict__ W_hh, int tid, bool comb) {
    for (int i = tid; i < 512 * 128; i += 256) {
        int r = i >> 7, k = i & 127;
        float v = W_hh[i];
        if (comb) v += W_ih[i];
        __half hh = __float2half(v);
        *(__half*)(smc + A_HI + aswz((unsigned)(r * 256 + k * 2))) = hh;
        int g = r >> 7, u = r & 127;
        if (g == 1)
            *(__half*)(smc + A_FLO + aswz((unsigned)(u * 256 + k * 2))) =
                __float2half(v - __half2float(hh));
        if (g == 2)
            *(__half*)(smc + A_GLO + aswz((unsigned)(u * 256 + k * 2))) =
                __float2half(v - __half2float(hh));
    }
}

__global__ void __launch_bounds__(256, 1) decoder_main(
    const float* __restrict__ latent, const float* __restrict__ fc_w, const float* __restrict__ fc_b,
    const float* __restrict__ W_ih,   const float* __restrict__ W_hh,
    const float* __restrict__ b_ih,   const float* __restrict__ b_hh,
    const float* __restrict__ Wo,     const float* __restrict__ bo,
    float* __restrict__ out)
{
    extern __shared__ char smc[];
    const unsigned smb = sm_u32(smc);
    const int tid = threadIdx.x, l = tid & 31, w = tid >> 5;
    const int cta = blockIdx.x;
    int bstart, nb;
    if (cta < 124) { bstart = cta * 14;                nb = 14; }
    else           { bstart = 1736 + (cta - 124) * 13; nb = 13; }

    // ---- init A with W_hh (step 0), Wo hi ----
    init_A(smc, W_ih, W_hh, tid, false);
    for (int i = tid; i < 64 * 128; i += 256) {
        int o = i >> 7, k = i & 127;
        *(__half*)(smc + A_WO + aswz((unsigned)(o * 256 + k * 2))) = __float2half(Wo[i]);
    }

    // ---- h0 = fc(latent), split hi/lo into B tiles (pad n -> 0) ----
    for (int i = tid; i < 2048; i += 256) {
        int k = i >> 4, n = i & 15;
        float a = 0.f;
        if (n < nb) {
            a = fc_b[k];
            const float* lp = latent + (size_t)(bstart + n) * Lq;
            const float* wp = fc_w + k * Lq;
#pragma unroll 8
            for (int j = 0; j < Lq; j++) a += lp[j] * wp[j];
        }
        __half hh = __float2half(a);
        *(__half*)(smc + H_HI + n * HSTB + k * 2) = hh;
        *(__half*)(smc + H_LO + n * HSTB + k * 2) = __float2half(a - __half2float(hh));
    }

    // ---- per-lane constants ----
    const int rr   = (l & 7) + ((l >> 3) & 1) * 8;      // ldmatrix row within 16
    const unsigned kxor = (unsigned)((l & 7) << 4);
    const unsigned kc0  = (unsigned)(((l >> 4) & 1) * 16);
    unsigned kbx[8];
#pragma unroll
    for (int kk = 0; kk < 8; kk++) kbx[kk] = ((unsigned)(kk * 32) + kc0) ^ kxor;

    unsigned rowA[4], rowGlo, rowFlo, rowWo;
#pragma unroll
    for (int g = 0; g < 4; g++)
        rowA[g] = smb + A_HI + (unsigned)((g * 128 + 16 * w + rr) * 256);
    rowGlo = smb + A_GLO + (unsigned)((16 * w + rr) * 256);
    rowFlo = smb + A_FLO + (unsigned)((16 * w + rr) * 256);
    rowWo  = smb + A_WO  + (unsigned)((16 * w + rr) * 256);   // valid only w<4

    const int nlo = l >> 2;            // 0..7
    const int kof = (l & 3) * 4;       // bytes
    const char* bb0 = smc + H_HI + (0 * 8 + nlo) * HSTB + kof;
    const char* bb1 = smc + H_HI + (1 * 8 + nlo) * HSTB + kof;

    const int u0 = 16 * w + (l >> 2), u1 = u0 + 8;
    float bia[2][4];
#pragma unroll
    for (int g = 0; g < 4; g++) {
        bia[0][g] = b_ih[g * 128 + u0] + b_hh[g * 128 + u0];
        bia[1][g] = b_ih[g * 128 + u1] + b_hh[g * 128 + u1];
    }
    float bo0 = 0.f, bo1 = 0.f;
    if (w < 4) { bo0 = bo[u0]; bo1 = bo[u1]; }
    const int nbase = 2 * (l & 3);
    float cS[8];
#pragma unroll
    for (int j = 0; j < 8; j++) cS[j] = 0.f;

    __syncthreads();

    // ---- main loop: iteration i uses B=h_i; gates -> h_{i+1}; out_{i-1} ----
    for (int i = 0; i < Tq; i++) {
        // load B fragments (hi & lo, 2 n-tiles x 8 k-steps)
        unsigned bh[2][8][2], bl[2][8][2];
#pragma unroll
        for (int kk = 0; kk < 8; kk++) {
            bh[0][kk][0] = *(const unsigned*)(bb0 + kk * 32);
            bh[0][kk][1] = *(const unsigned*)(bb0 + kk * 32 + 16);
            bh[1][kk][0] = *(const unsigned*)(bb1 + kk * 32);
            bh[1][kk][1] = *(const unsigned*)(bb1 + kk * 32 + 16);
            bl[0][kk][0] = *(const unsigned*)(bb0 + 4352 + kk * 32);
            bl[0][kk][1] = *(const unsigned*)(bb0 + 4352 + kk * 32 + 16);
            bl[1][kk][0] = *(const unsigned*)(bb1 + 4352 + kk * 32);
            bl[1][kk][1] = *(const unsigned*)(bb1 + 4352 + kk * 32 + 16);
        }

        float D[4][2][4];
#pragma unroll
        for (int g = 0; g < 4; g++)
#pragma unroll
            for (int nt = 0; nt < 2; nt++)
#pragma unroll
                for (int q = 0; q < 4; q++) D[g][nt][q] = 0.f;

        // gate hi passes (A-hi @ (Bhi + Blo))
#pragma unroll
        for (int g = 0; g < 4; g++)
#pragma unroll
            for (int kk = 0; kk < 8; kk++) {
                unsigned a[4];
                ldmx4(a, rowA[g] + kbx[kk]);
                mma16(D[g][0], a, bh[0][kk][0], bh[0][kk][1]);
                mma16(D[g][0], a, bl[0][kk][0], bl[0][kk][1]);
                mma16(D[g][1], a, bh[1][kk][0], bh[1][kk][1]);
                mma16(D[g][1], a, bl[1][kk][0], bl[1][kk][1]);
            }
        // f-lo and g-lo passes (A-lo @ Bhi)
#pragma unroll
        for (int kk = 0; kk < 8; kk++) {
            unsigned a[4];
            ldmx4(a, rowFlo + kbx[kk]);
            mma16(D[1][0], a, bh[0][kk][0], bh[0][kk][1]);
            mma16(D[1][1], a, bh[1][kk][0], bh[1][kk][1]);
        }
#pragma unroll
        for (int kk = 0; kk < 8; kk++) {
            unsigned a[4];
            ldmx4(a, rowGlo + kbx[kk]);
            mma16(D[2][0], a, bh[0][kk][0], bh[0][kk][1]);
            mma16(D[2][1], a, bh[1][kk][0], bh[1][kk][1]);
        }
        // out tiles (warps 0-3): Wo-hi @ (Bhi + Blo)
        float Dw[2][4];
#pragma unroll
        for (int nt = 0; nt < 2; nt++)
#pragma unroll
            for (int q = 0; q < 4; q++) Dw[nt][q] = 0.f;
        if (w < 4) {
#pragma unroll
            for (int kk = 0; kk < 8; kk++) {
                unsigned a[4];
                ldmx4(a, rowWo + kbx[kk]);
                mma16(Dw[0], a, bh[0][kk][0], bh[0][kk][1]);
                mma16(Dw[0], a, bl[0][kk][0], bl[0][kk][1]);
                mma16(Dw[1], a, bh[1][kk][0], bh[1][kk][1]);
                mma16(Dw[1], a, bl[1][kk][0], bl[1][kk][1]);
            }
        }
        __syncthreads();   // all B reads done before h overwrite

        // ---- elementwise: c,h update; split-store h_{i+1} ----
#pragma unroll
        for (int nt = 0; nt < 2; nt++)
#pragma unroll
            for (int q = 0; q < 4; q++) {
                int ui = q >> 1;
                int u  = ui ? u1 : u0;
                int n  = nt * 8 + nbase + (q & 1);
                float I = sigf(D[0][nt][q] + bia[ui][0]);
                float F = sigf(D[1][nt][q] + bia[ui][1]);
                float G = tanhf2(D[2][nt][q] + bia[ui][2]);
                float O = sigf(D[3][nt][q] + bia[ui][3]);
                float c = F * cS[nt * 4 + q] + I * G;
                cS[nt * 4 + q] = c;
                float h = O * tanhf2(c);
                __half hh = __float2half(h);
                __half hl = __float2half(h - __half2float(hh));
                *(__half*)(smc + H_HI + n * HSTB + u * 2) = hh;
                *(__half*)(smc + H_LO + n * HSTB + u * 2) = hl;
            }

        // ---- store out[i-1] ----
        if (i > 0 && w < 4) {
#pragma unroll
            for (int nt = 0; nt < 2; nt++)
#pragma unroll
                for (int q = 0; q < 4; q++) {
                    int n = nt * 8 + nbase + (q & 1);
                    int o = (q >> 1) ? u1 : u0;
                    if (n < nb)
                        out[(((size_t)(bstart + n)) * Tq + (i - 1)) * Oq + o] =
                            Dw[nt][q] + ((q >> 1) ? bo1 : bo0);
                }
        }
        __syncthreads();

        // after step 0: rewrite A tiles with Wc = W_ih + W_hh
        if (i == 0) {
            init_A(smc, W_ih, W_hh, tid, true);
            __syncthreads();
        }
    }

    // ---- tail: out[T-1] = Wo @ h_T ----
    if (w < 4) {
        unsigned bh[2][8][2], bl[2][8][2];
#pragma unroll
        for (int kk = 0; kk < 8; kk++) {
            bh[0][kk][0] = *(const unsigned*)(bb0 + kk * 32);
            bh[0][kk][1] = *(const unsigned*)(bb0 + kk * 32 + 16);
            bh[1][kk][0] = *(const unsigned*)(bb1 + kk * 32);
            bh[1][kk][1] = *(const unsigned*)(bb1 + kk * 32 + 16);
            bl[0][kk][0] = *(const unsigned*)(bb0 + 4352 + kk * 32);
            bl[0][kk][1] = *(const unsigned*)(bb0 + 4352 + kk * 32 + 16);
            bl[1][kk][0] = *(const unsigned*)(bb1 + 4352 + kk * 32);
            bl[1][kk][1] = *(const unsigned*)(bb1 + 4352 + kk * 32 + 16);
        }
        float Dw[2][4];
#pragma unroll
        for (int nt = 0; nt < 2; nt++)
#pragma unroll
            for (int q = 0; q < 4; q++) Dw[nt][q] = 0.f;
#pragma unroll
        for (int kk = 0; kk < 8; kk++) {
            unsigned a[4];
            ldmx4(a, rowWo + kbx[kk]);
            mma16(Dw[0], a, bh[0][kk][0], bh[0][kk][1]);
            mma16(Dw[0], a, bl[0][kk][0], bl[0][kk][1]);
            mma16(Dw[1], a, bh[1][kk][0], bh[1][kk][1]);
            mma16(Dw[1], a, bl[1][kk][0], bl[1][kk][1]);
        }
#pragma unroll
        for (int nt = 0; nt < 2; nt++)
#pragma unroll
            for (int q = 0; q < 4; q++) {
                int n = nt * 8 + nbase + (q & 1);
                int o = (q >> 1) ? u1 : u0;
                if (n < nb)
                    out[(((size_t)(bstart + n)) * Tq + (Tq - 1)) * Oq + o] =
                        Dw[nt][q] + ((q >> 1) ? bo1 : bo0);
            }
    }
}

extern "C" void kernel_launch(void* const* d_in, const int* in_sizes, int n_in,
                              void* d_out, int out_size) {
    const float* latent = (const float*)d_in[0];
    const float* fc_w   = (const float*)d_in[1];
    const float* fc_b   = (const float*)d_in[2];
    const float* W_ih   = (const float*)d_in[3];
    const float* W_hh   = (const float*)d_in[4];
    const float* b_ih   = (const float*)d_in[5];
    const float* b_hh   = (const float*)d_in[6];
    const float* Wo     = (const float*)d_in[7];
    const float* bo     = (const float*)d_in[8];
    float* out = (float*)d_out;

    cudaFuncSetAttribute(decoder_main,
                         cudaFuncAttributeMaxDynamicSharedMemorySize, SMEM_BYTES);

    decoder_main<<<148, 256, SMEM_BYTES>>>(latent, fc_w, fc_b, W_ih, W_hh,
                                           b_ih, b_hh, Wo, bo, out);
}